// round 1
// baseline (speedup 1.0000x reference)
#include <cuda_runtime.h>
#include <cstdint>

// CRF_1254130451065: energy[B,T,U] = x[B,T,D] @ kernel[D,U] + bias[U]
//                    + start_mask*left[U] + end_mask*right[U]
// B=64, T=512, D=1024, U=128 -> GEMM M=32768, K=1024, N=128 (fp32)
//
// Round 0: SIMT SGEMM using packed fma.rn.f32x2 (2x fp32 FMA throughput on
// sm_103a vs scalar FFMA; only reachable via PTX). 128x128x16 block tile,
// 8x8 per-thread microtile, fused epilogue.

#define M_TOT 32768
#define K_TOT 1024
#define N_TOT 128
#define T_LEN 512

#define BM 128
#define BN 128
#define BK 16
#define TM 8
#define TN 8
#define NTHREADS 256   // (BM/TM)*(BN/TN)

__device__ __forceinline__ unsigned long long pack2(float lo, float hi) {
    unsigned long long r;
    asm("mov.b64 %0, {%1, %2};" : "=l"(r) : "f"(lo), "f"(hi));
    return r;
}

__device__ __forceinline__ float2 unpack2(unsigned long long v) {
    float2 r;
    asm("mov.b64 {%0, %1}, %2;" : "=f"(r.x), "=f"(r.y) : "l"(v));
    return r;
}

// d = a * b + d on packed f32x2 (2 fp32 FMAs in one instruction)
__device__ __forceinline__ void ffma2(unsigned long long& d,
                                      unsigned long long a,
                                      unsigned long long b) {
    asm("fma.rn.f32x2 %0, %1, %2, %0;" : "+l"(d) : "l"(a), "l"(b));
}

__global__ __launch_bounds__(NTHREADS, 2)
void crf_gemm_kernel(const float* __restrict__ x,
                     const int* __restrict__ mask,
                     const float* __restrict__ w,
                     const float* __restrict__ bias,
                     const float* __restrict__ lb,
                     const float* __restrict__ rb,
                     float* __restrict__ out) {
    // A tile transposed: As[k][m], padded to reduce store bank conflicts.
    __shared__ float As[BK][BM + 4];
    __shared__ float Bs[BK][BN];

    const int tid = threadIdx.x;
    const int tx = tid & 15;        // 0..15 -> N microtile
    const int ty = tid >> 4;        // 0..15 -> M microtile
    const int rowBase = blockIdx.x * BM;

    unsigned long long acc[TM][TN / 2];
#pragma unroll
    for (int i = 0; i < TM; i++)
#pragma unroll
        for (int j = 0; j < TN / 2; j++) acc[i][j] = 0ULL;

    for (int kt = 0; kt < K_TOT; kt += BK) {
        // ---- load A tile: 128 rows x 16 cols = 512 float4 (2 per thread) ----
#pragma unroll
        for (int l = 0; l < 2; l++) {
            int idx = tid + l * NTHREADS;
            int r = idx >> 2;        // 0..127
            int c4 = idx & 3;        // 0..3  -> cols c4*4 .. c4*4+3
            float4 v = *reinterpret_cast<const float4*>(
                &x[(size_t)(rowBase + r) * K_TOT + kt + c4 * 4]);
            As[c4 * 4 + 0][r] = v.x;
            As[c4 * 4 + 1][r] = v.y;
            As[c4 * 4 + 2][r] = v.z;
            As[c4 * 4 + 3][r] = v.w;
        }
        // ---- load B tile: 16 rows x 128 cols = 512 float4 (2 per thread) ----
#pragma unroll
        for (int l = 0; l < 2; l++) {
            int idx = tid + l * NTHREADS;
            int r = idx >> 5;        // 0..15
            int c4 = idx & 31;       // 0..31
            float4 v = *reinterpret_cast<const float4*>(
                &w[(size_t)(kt + r) * N_TOT + c4 * 4]);
            *reinterpret_cast<float4*>(&Bs[r][c4 * 4]) = v;
        }
        __syncthreads();

        // ---- compute ----
#pragma unroll
        for (int k = 0; k < BK; k++) {
            float4 a0 = *reinterpret_cast<const float4*>(&As[k][ty * TM]);
            float4 a1 = *reinterpret_cast<const float4*>(&As[k][ty * TM + 4]);
            float4 b0 = *reinterpret_cast<const float4*>(&Bs[k][tx * TN]);
            float4 b1 = *reinterpret_cast<const float4*>(&Bs[k][tx * TN + 4]);

            unsigned long long bb[4];
            bb[0] = pack2(b0.x, b0.y);
            bb[1] = pack2(b0.z, b0.w);
            bb[2] = pack2(b1.x, b1.y);
            bb[3] = pack2(b1.z, b1.w);

            float av[8] = {a0.x, a0.y, a0.z, a0.w, a1.x, a1.y, a1.z, a1.w};
#pragma unroll
            for (int i = 0; i < TM; i++) {
                unsigned long long aa = pack2(av[i], av[i]);
#pragma unroll
                for (int j = 0; j < 4; j++) ffma2(acc[i][j], aa, bb[j]);
            }
        }
        __syncthreads();
    }

    // ---- fused epilogue: bias + boundary masks, then store ----
#pragma unroll
    for (int i = 0; i < TM; i++) {
        int m = rowBase + ty * TM + i;
        int b = m >> 9;              // m / T_LEN
        int t = m & (T_LEN - 1);     // m % T_LEN
        const int* mrow = mask + b * T_LEN;
        int mv = mrow[t];
        int prev = (t > 0) ? mrow[t - 1] : 0;
        int next = (t < T_LEN - 1) ? mrow[t + 1] : 0;
        float sf = (mv > prev) ? 1.0f : 0.0f;   // first valid step
        float ef = (next > mv) ? 1.0f : 0.0f;   // as written in source
        float* orow = out + (size_t)m * N_TOT + tx * TN;
#pragma unroll
        for (int j = 0; j < 4; j++) {
            float2 v = unpack2(acc[i][j]);
            int n = tx * TN + j * 2;
            v.x += __ldg(&bias[n])     + sf * __ldg(&lb[n])     + ef * __ldg(&rb[n]);
            v.y += __ldg(&bias[n + 1]) + sf * __ldg(&lb[n + 1]) + ef * __ldg(&rb[n + 1]);
            *reinterpret_cast<float2*>(&orow[j * 2]) = v;
        }
    }
}

extern "C" void kernel_launch(void* const* d_in, const int* in_sizes, int n_in,
                              void* d_out, int out_size) {
    const float* x    = (const float*)d_in[0];  // [B,T,D] fp32
    const int*   mask = (const int*)d_in[1];    // [B,T] int32
    const float* w    = (const float*)d_in[2];  // [D,U] fp32
    const float* bias = (const float*)d_in[3];  // [U] fp32
    const float* lb   = (const float*)d_in[4];  // [U] fp32
    const float* rb   = (const float*)d_in[5];  // [U] fp32
    float* out = (float*)d_out;                 // [B,T,U] fp32

    dim3 grid(M_TOT / BM);   // 256 CTAs
    dim3 block(NTHREADS);
    crf_gemm_kernel<<<grid, block>>>(x, mask, w, bias, lb, rb, out);
}

// round 4
// speedup vs baseline: 2.3444x; 2.3444x over previous
#include <cuda_runtime.h>
#include <cuda_bf16.h>
#include <cstdint>

// CRF: energy[B,T,U] = x[B,T,D] @ w[D,U] + bias + start*lb + end*rb
// GEMM M=32768 K=1024 N=128 fp32, via mma.sync bf16 hi/lo 3-pass split.
// (tcgen05 is ptxas-rejected on this build's compute_103 target; mma.sync
//  m16n8k16 bf16 is sm_80+ baseline and runs on Blackwell tensor cores.)
// R3 fix: B-tile prefetch indexed n=idx>>1/q=idx&1 (n up to 255, OOB read
// of g_whi). Correct: 4 uint4 per 32-elem row -> n=idx>>2, q=idx&3.

#define M_TOT 32768
#define K_TOT 1024
#define N_TOT 128
#define T_LEN 512
#define BM 128
#define BK 32
#define NCHUNK (K_TOT / BK)   // 32
#define NTILES (M_TOT / BM)   // 256
#define NTHREADS 256

// smem row stride: 40 bf16 = 80 bytes (pads 32-elem rows; conflict-free ldmatrix)
#define ROWB 80
#define TILE_BYTES (128 * ROWB)     // 10240 per matrix
#define SM_AHI 0
#define SM_ALO (1 * TILE_BYTES)
#define SM_BHI (2 * TILE_BYTES)
#define SM_BLO (3 * TILE_BYTES)
#define SM_BIAS (4 * TILE_BYTES)          // 40960
#define SM_LB   (SM_BIAS + 512)
#define SM_RB   (SM_BIAS + 1024)
#define SM_TOTAL (SM_BIAS + 1536)         // 42496 B (static)

__device__ __forceinline__ uint32_t smem_u32(const void* p) {
    uint32_t a;
    asm("{ .reg .u64 t; cvta.to.shared.u64 t, %1; cvt.u32.u64 %0, t; }" : "=r"(a) : "l"(p));
    return a;
}

__device__ __forceinline__ void ldsm_x4(uint32_t (&r)[4], uint32_t addr) {
    asm volatile("ldmatrix.sync.aligned.m8n8.x4.shared.b16 {%0,%1,%2,%3}, [%4];"
                 : "=r"(r[0]), "=r"(r[1]), "=r"(r[2]), "=r"(r[3]) : "r"(addr));
}

__device__ __forceinline__ void mma16816(float (&c)[4], const uint32_t (&a)[4],
                                         uint32_t b0, uint32_t b1) {
    asm volatile(
        "mma.sync.aligned.m16n8k16.row.col.f32.bf16.bf16.f32 "
        "{%0,%1,%2,%3}, {%4,%5,%6,%7}, {%8,%9}, {%0,%1,%2,%3};"
        : "+f"(c[0]), "+f"(c[1]), "+f"(c[2]), "+f"(c[3])
        : "r"(a[0]), "r"(a[1]), "r"(a[2]), "r"(a[3]), "r"(b0), "r"(b1));
}

__device__ __forceinline__ uint32_t pk(__nv_bfloat16 a, __nv_bfloat16 b) {
    __nv_bfloat162 t = __halves2bfloat162(a, b);
    return *reinterpret_cast<uint32_t*>(&t);
}

// ---- device scratch: w split + transposed to [N, K] bf16 (K-major) ----
__device__ __align__(16) __nv_bfloat16 g_whi[N_TOT * K_TOT];
__device__ __align__(16) __nv_bfloat16 g_wlo[N_TOT * K_TOT];

__global__ void prep_w_kernel(const float* __restrict__ w) {
    int idx = blockIdx.x * blockDim.x + threadIdx.x;   // n*1024 + k
    if (idx >= N_TOT * K_TOT) return;
    int n = idx >> 10, k = idx & 1023;
    float v = w[(size_t)k * N_TOT + n];
    __nv_bfloat16 h = __float2bfloat16(v);
    g_whi[idx] = h;
    g_wlo[idx] = __float2bfloat16(v - __bfloat162float(h));
}

__global__ __launch_bounds__(NTHREADS)
void crf_mma_kernel(const float* __restrict__ x, const int* __restrict__ mask,
                    const float* __restrict__ bias, const float* __restrict__ lb,
                    const float* __restrict__ rb, float* __restrict__ out) {
    __shared__ __align__(128) char sm[SM_TOTAL];
    const uint32_t smb = smem_u32(sm);

    const int tid = threadIdx.x;
    const int wid = tid >> 5, lane = tid & 31;
    const int wm = wid & 3, wn = wid >> 2;      // 4 M-warps x 2 N-warps
    const int rowBase = blockIdx.x * BM;

    if (tid < N_TOT) {
        *(float*)(sm + SM_BIAS + tid * 4) = bias[tid];
        *(float*)(sm + SM_LB + tid * 4) = lb[tid];
        *(float*)(sm + SM_RB + tid * 4) = rb[tid];
    }

    float acc[2][8][4];
#pragma unroll
    for (int i = 0; i < 2; i++)
#pragma unroll
        for (int j = 0; j < 8; j++)
#pragma unroll
            for (int v = 0; v < 4; v++) acc[i][j][v] = 0.0f;

    // ldmatrix per-lane addresses (element offsets within tiles)
    const int grp = lane >> 3, lr = lane & 7;
    // A frags: mat0=(mLo,kLo) mat1=(mHi,kLo) mat2=(mLo,kHi) mat3=(mHi,kHi)
    const uint32_t aRow = wm * 32 + (grp & 1) * 8 + lr;
    const uint32_t aKof = (grp >> 1) * 8;
    // B frags: mat0=(nLo,kLo) mat1=(nLo,kHi) mat2=(nHi,kLo) mat3=(nHi,kHi)
    const uint32_t bRow = wn * 64 + (grp >> 1) * 8 + lr;
    const uint32_t bKof = (grp & 1) * 8;

    // ---- prefetch chunk 0 ----
    float4 aR[4];
    uint4 bhR[2], blR[2];
#pragma unroll
    for (int i = 0; i < 4; i++) {
        int idx = i * NTHREADS + tid;
        int r = idx >> 3, c4 = idx & 7;
        aR[i] = *reinterpret_cast<const float4*>(x + (size_t)(rowBase + r) * K_TOT + c4 * 4);
    }
#pragma unroll
    for (int i = 0; i < 2; i++) {
        int idx = i * NTHREADS + tid;
        int n = idx >> 2, q = idx & 3;                       // 128 rows x 4 uint4
        bhR[i] = *reinterpret_cast<const uint4*>(g_whi + (size_t)n * K_TOT + q * 8);
        blR[i] = *reinterpret_cast<const uint4*>(g_wlo + (size_t)n * K_TOT + q * 8);
    }

#pragma unroll 1
    for (int c = 0; c < NCHUNK; c++) {
        __syncthreads();   // previous compute done before overwriting smem
        // ---- STS A (convert fp32 -> bf16 hi/lo) ----
#pragma unroll
        for (int i = 0; i < 4; i++) {
            int idx = i * NTHREADS + tid;
            int r = idx >> 3, c4 = idx & 7;
            float4 v = aR[i];
            __nv_bfloat16 h0 = __float2bfloat16(v.x), h1 = __float2bfloat16(v.y);
            __nv_bfloat16 h2 = __float2bfloat16(v.z), h3 = __float2bfloat16(v.w);
            uint2 hh; hh.x = pk(h0, h1); hh.y = pk(h2, h3);
            uint2 ll;
            ll.x = pk(__float2bfloat16(v.x - __bfloat162float(h0)),
                      __float2bfloat16(v.y - __bfloat162float(h1)));
            ll.y = pk(__float2bfloat16(v.z - __bfloat162float(h2)),
                      __float2bfloat16(v.w - __bfloat162float(h3)));
            uint32_t off = (uint32_t)(r * ROWB + c4 * 8);
            *(uint2*)(sm + SM_AHI + off) = hh;
            *(uint2*)(sm + SM_ALO + off) = ll;
        }
        // ---- STS B ----
#pragma unroll
        for (int i = 0; i < 2; i++) {
            int idx = i * NTHREADS + tid;
            int n = idx >> 2, q = idx & 3;
            uint32_t off = (uint32_t)(n * ROWB + q * 16);
            *(uint4*)(sm + SM_BHI + off) = bhR[i];
            *(uint4*)(sm + SM_BLO + off) = blR[i];
        }
        __syncthreads();

        // ---- prefetch chunk c+1 (overlaps MMA below) ----
        if (c + 1 < NCHUNK) {
            const int kt = (c + 1) * BK;
#pragma unroll
            for (int i = 0; i < 4; i++) {
                int idx = i * NTHREADS + tid;
                int r = idx >> 3, c4 = idx & 7;
                aR[i] = *reinterpret_cast<const float4*>(
                    x + (size_t)(rowBase + r) * K_TOT + kt + c4 * 4);
            }
#pragma unroll
            for (int i = 0; i < 2; i++) {
                int idx = i * NTHREADS + tid;
                int n = idx >> 2, q = idx & 3;
                bhR[i] = *reinterpret_cast<const uint4*>(g_whi + (size_t)n * K_TOT + kt + q * 8);
                blR[i] = *reinterpret_cast<const uint4*>(g_wlo + (size_t)n * K_TOT + kt + q * 8);
            }
        }

        // ---- compute: 2 k16-steps, 3 passes each ----
#pragma unroll
        for (int ks = 0; ks < 2; ks++) {
            uint32_t ahi[2][4], alo[2][4];
#pragma unroll
            for (int mt = 0; mt < 2; mt++) {
                uint32_t ao = (aRow + mt * 16) * ROWB + (ks * 16 + aKof) * 2;
                ldsm_x4(ahi[mt], smb + SM_AHI + ao);
                ldsm_x4(alo[mt], smb + SM_ALO + ao);
            }
            uint32_t bhi[4][4], blo[4][4];
#pragma unroll
            for (int np = 0; np < 4; np++) {
                uint32_t bo = (bRow + np * 16) * ROWB + (ks * 16 + bKof) * 2;
                ldsm_x4(bhi[np], smb + SM_BHI + bo);
                ldsm_x4(blo[np], smb + SM_BLO + bo);
            }
#pragma unroll
            for (int mt = 0; mt < 2; mt++)
#pragma unroll
                for (int np = 0; np < 4; np++) {
                    mma16816(acc[mt][2 * np + 0], ahi[mt], bhi[np][0], bhi[np][1]);
                    mma16816(acc[mt][2 * np + 1], ahi[mt], bhi[np][2], bhi[np][3]);
                    mma16816(acc[mt][2 * np + 0], alo[mt], bhi[np][0], bhi[np][1]);
                    mma16816(acc[mt][2 * np + 1], alo[mt], bhi[np][2], bhi[np][3]);
                    mma16816(acc[mt][2 * np + 0], ahi[mt], blo[np][0], blo[np][1]);
                    mma16816(acc[mt][2 * np + 1], ahi[mt], blo[np][2], blo[np][3]);
                }
        }
    }

    // ---- fused epilogue ----
    const float* sb = (const float*)(sm + SM_BIAS);
    const float* sl = (const float*)(sm + SM_LB);
    const float* sr = (const float*)(sm + SM_RB);
    const int colBase = wn * 64 + (lane & 3) * 2;
#pragma unroll
    for (int mt = 0; mt < 2; mt++) {
#pragma unroll
        for (int h = 0; h < 2; h++) {
            int m = rowBase + wm * 32 + mt * 16 + h * 8 + (lane >> 2);
            int bb = m >> 9, t = m & (T_LEN - 1);
            const int* mrow = mask + bb * T_LEN;
            int mv = mrow[t];
            int prev = t ? mrow[t - 1] : 0;
            int nxt = (t < T_LEN - 1) ? mrow[t + 1] : 0;
            float sf = (mv > prev) ? 1.0f : 0.0f;
            float ef = (nxt > mv) ? 1.0f : 0.0f;
            float* orow = out + (size_t)m * N_TOT;
#pragma unroll
            for (int nt = 0; nt < 8; nt++) {
                int col = colBase + nt * 8;
                float2 v;
                v.x = acc[mt][nt][h * 2 + 0] + sb[col] + sf * sl[col] + ef * sr[col];
                v.y = acc[mt][nt][h * 2 + 1] + sb[col + 1] + sf * sl[col + 1] + ef * sr[col + 1];
                *reinterpret_cast<float2*>(orow + col) = v;
            }
        }
    }
}

extern "C" void kernel_launch(void* const* d_in, const int* in_sizes, int n_in,
                              void* d_out, int out_size) {
    const float* x    = (const float*)d_in[0];  // [B,T,D]
    const int*   mask = (const int*)d_in[1];    // [B,T]
    const float* w    = (const float*)d_in[2];  // [D,U]
    const float* bias = (const float*)d_in[3];
    const float* lb   = (const float*)d_in[4];
    const float* rb   = (const float*)d_in[5];
    float* out = (float*)d_out;

    prep_w_kernel<<<(N_TOT * K_TOT + 255) / 256, 256>>>(w);
    crf_mma_kernel<<<NTILES, NTHREADS>>>(x, mask, bias, lb, rb, out);
}

// round 5
// speedup vs baseline: 3.0134x; 1.2853x over previous
#include <cuda_runtime.h>
#include <cuda_fp16.h>
#include <cstdint>

// CRF: energy[B,T,U] = x[B,T,D] @ w[D,U] + bias + start*lb + end*rb
// GEMM M=32768 K=1024 N=128 fp32 via mma.sync fp16 2-pass split:
//   acc = (A_hi + A_lo) * B,  A_hi/A_lo = fp16 split of x, B = fp16(w).
//   error = x . (w - fp16(w)) -> rel_err ~3-5e-4 (calibrated vs R4).
// Double-buffered smem, one __syncthreads per chunk; LDG issued 2 chunks ahead.

#define M_TOT 32768
#define K_TOT 1024
#define N_TOT 128
#define T_LEN 512
#define BM 128
#define BK 32
#define NCHUNK (K_TOT / BK)   // 32
#define NTILES (M_TOT / BM)   // 256
#define NTHREADS 256

#define ROWB 80                       // 80-byte row stride (pads 64B rows)
#define TILE_BYTES (128 * ROWB)       // 10240
#define A_HI 0
#define A_LO TILE_BYTES
#define B_OFF (2 * TILE_BYTES)
#define BUF_STRIDE (3 * TILE_BYTES)   // 30720
#define SM_BIAS (2 * BUF_STRIDE)      // 61440
#define SM_LB   (SM_BIAS + 512)
#define SM_RB   (SM_BIAS + 1024)
#define SM_TOTAL (SM_BIAS + 1536)     // 62976 (dynamic)

__device__ __forceinline__ uint32_t smem_u32(const void* p) {
    uint32_t a;
    asm("{ .reg .u64 t; cvta.to.shared.u64 t, %1; cvt.u32.u64 %0, t; }" : "=r"(a) : "l"(p));
    return a;
}

__device__ __forceinline__ void ldsm_x4(uint32_t (&r)[4], uint32_t addr) {
    asm volatile("ldmatrix.sync.aligned.m8n8.x4.shared.b16 {%0,%1,%2,%3}, [%4];"
                 : "=r"(r[0]), "=r"(r[1]), "=r"(r[2]), "=r"(r[3]) : "r"(addr));
}

__device__ __forceinline__ void mma16816(float (&c)[4], const uint32_t (&a)[4],
                                         uint32_t b0, uint32_t b1) {
    asm volatile(
        "mma.sync.aligned.m16n8k16.row.col.f32.f16.f16.f32 "
        "{%0,%1,%2,%3}, {%4,%5,%6,%7}, {%8,%9}, {%0,%1,%2,%3};"
        : "+f"(c[0]), "+f"(c[1]), "+f"(c[2]), "+f"(c[3])
        : "r"(a[0]), "r"(a[1]), "r"(a[2]), "r"(a[3]), "r"(b0), "r"(b1));
}

__device__ __forceinline__ uint32_t pk(__half a, __half b) {
    __half2 t = __halves2half2(a, b);
    return *reinterpret_cast<uint32_t*>(&t);
}

// w transposed to [N, K] fp16 (K-major, "col" operand for mma.sync)
__device__ __align__(16) __half g_wh[N_TOT * K_TOT];

__global__ void prep_w_kernel(const float* __restrict__ w) {
    int idx = blockIdx.x * blockDim.x + threadIdx.x;   // n*1024 + k
    if (idx >= N_TOT * K_TOT) return;
    int n = idx >> 10, k = idx & 1023;
    g_wh[idx] = __float2half(w[(size_t)k * N_TOT + n]);
}

__global__ __launch_bounds__(NTHREADS)
void crf_mma_kernel(const float* __restrict__ x, const int* __restrict__ mask,
                    const float* __restrict__ bias, const float* __restrict__ lb,
                    const float* __restrict__ rb, float* __restrict__ out) {
    extern __shared__ __align__(128) char sm[];
    const uint32_t smb = smem_u32(sm);

    const int tid = threadIdx.x;
    const int wid = tid >> 5, lane = tid & 31;
    const int wm = wid & 3, wn = wid >> 2;      // 4 M-warps x 2 N-warps
    const int rowBase = blockIdx.x * BM;

    if (tid < N_TOT) {
        *(float*)(sm + SM_BIAS + tid * 4) = bias[tid];
        *(float*)(sm + SM_LB + tid * 4) = lb[tid];
        *(float*)(sm + SM_RB + tid * 4) = rb[tid];
    }

    float acc[2][8][4];
#pragma unroll
    for (int i = 0; i < 2; i++)
#pragma unroll
        for (int j = 0; j < 8; j++)
#pragma unroll
            for (int v = 0; v < 4; v++) acc[i][j][v] = 0.0f;

    // ldmatrix per-lane source rows (same mapping as R4, fp16 payload)
    const int grp = lane >> 3, lr = lane & 7;
    const uint32_t aRow = wm * 32 + (grp & 1) * 8 + lr;
    const uint32_t aKof = (grp >> 1) * 8;
    const uint32_t bRow = wn * 64 + (grp >> 1) * 8 + lr;
    const uint32_t bKof = (grp & 1) * 8;

    float4 aR[4];
    uint4 bR[2];

    // ---- helpers as lambdas ----
    auto load_regs = [&](int c) {
        const int kt = c * BK;
#pragma unroll
        for (int i = 0; i < 4; i++) {
            int idx = i * NTHREADS + tid;
            int r = idx >> 3, c4 = idx & 7;
            aR[i] = *reinterpret_cast<const float4*>(
                x + (size_t)(rowBase + r) * K_TOT + kt + c4 * 4);
        }
#pragma unroll
        for (int i = 0; i < 2; i++) {
            int idx = i * NTHREADS + tid;
            int n = idx >> 2, q = idx & 3;     // 128 rows x 4 uint4 per 32-fp16 row
            bR[i] = *reinterpret_cast<const uint4*>(g_wh + (size_t)n * K_TOT + kt + q * 8);
        }
    };
    auto sts_buf = [&](int buf) {
        char* base = sm + buf * BUF_STRIDE;
#pragma unroll
        for (int i = 0; i < 4; i++) {
            int idx = i * NTHREADS + tid;
            int r = idx >> 3, c4 = idx & 7;
            float4 v = aR[i];
            __half h0 = __float2half(v.x), h1 = __float2half(v.y);
            __half h2 = __float2half(v.z), h3 = __float2half(v.w);
            uint2 hh; hh.x = pk(h0, h1); hh.y = pk(h2, h3);
            uint2 ll;
            ll.x = pk(__float2half(v.x - __half2float(h0)),
                      __float2half(v.y - __half2float(h1)));
            ll.y = pk(__float2half(v.z - __half2float(h2)),
                      __float2half(v.w - __half2float(h3)));
            uint32_t off = (uint32_t)(r * ROWB + c4 * 8);
            *(uint2*)(base + A_HI + off) = hh;
            *(uint2*)(base + A_LO + off) = ll;
        }
#pragma unroll
        for (int i = 0; i < 2; i++) {
            int idx = i * NTHREADS + tid;
            int n = idx >> 2, q = idx & 3;
            *(uint4*)(base + B_OFF + (uint32_t)(n * ROWB + q * 16)) = bR[i];
        }
    };

    // ---- prologue ----
    load_regs(0);
    sts_buf(0);
    load_regs(1);
    __syncthreads();

#pragma unroll 1
    for (int c = 0; c < NCHUNK; c++) {
        const uint32_t cb = smb + (c & 1) * BUF_STRIDE;
        if (c + 1 < NCHUNK) sts_buf((c + 1) & 1);
        if (c + 2 < NCHUNK) load_regs(c + 2);

        // ---- compute chunk c: 2 k16-steps, hi pass then lo pass ----
#pragma unroll
        for (int ks = 0; ks < 2; ks++) {
            uint32_t af[2][2][4];   // [mt][hi/lo]
#pragma unroll
            for (int mt = 0; mt < 2; mt++) {
                uint32_t ao = (aRow + mt * 16) * ROWB + (ks * 16 + aKof) * 2;
                ldsm_x4(af[mt][0], cb + A_HI + ao);
                ldsm_x4(af[mt][1], cb + A_LO + ao);
            }
            uint32_t bf[4][4];
#pragma unroll
            for (int np = 0; np < 4; np++) {
                uint32_t bo = (bRow + np * 16) * ROWB + (ks * 16 + bKof) * 2;
                ldsm_x4(bf[np], cb + B_OFF + bo);
            }
#pragma unroll
            for (int mt = 0; mt < 2; mt++)
#pragma unroll
                for (int np = 0; np < 4; np++) {
                    mma16816(acc[mt][2 * np + 0], af[mt][0], bf[np][0], bf[np][1]);
                    mma16816(acc[mt][2 * np + 1], af[mt][0], bf[np][2], bf[np][3]);
                }
#pragma unroll
            for (int mt = 0; mt < 2; mt++)
#pragma unroll
                for (int np = 0; np < 4; np++) {
                    mma16816(acc[mt][2 * np + 0], af[mt][1], bf[np][0], bf[np][1]);
                    mma16816(acc[mt][2 * np + 1], af[mt][1], bf[np][2], bf[np][3]);
                }
        }
        __syncthreads();
    }

    // ---- fused epilogue ----
    const float* sb = (const float*)(sm + SM_BIAS);
    const float* sl = (const float*)(sm + SM_LB);
    const float* sr = (const float*)(sm + SM_RB);
    const int colBase = wn * 64 + (lane & 3) * 2;
#pragma unroll
    for (int mt = 0; mt < 2; mt++) {
#pragma unroll
        for (int h = 0; h < 2; h++) {
            int m = rowBase + wm * 32 + mt * 16 + h * 8 + (lane >> 2);
            int bb = m >> 9, t = m & (T_LEN - 1);
            const int* mrow = mask + bb * T_LEN;
            int mv = mrow[t];
            int prev = t ? mrow[t - 1] : 0;
            int nxt = (t < T_LEN - 1) ? mrow[t + 1] : 0;
            float sf = (mv > prev) ? 1.0f : 0.0f;
            float ef = (nxt > mv) ? 1.0f : 0.0f;
            float* orow = out + (size_t)m * N_TOT;
#pragma unroll
            for (int nt = 0; nt < 8; nt++) {
                int col = colBase + nt * 8;
                float2 v;
                v.x = acc[mt][nt][h * 2 + 0] + sb[col] + sf * sl[col] + ef * sr[col];
                v.y = acc[mt][nt][h * 2 + 1] + sb[col + 1] + sf * sl[col + 1] + ef * sr[col + 1];
                *reinterpret_cast<float2*>(orow + col) = v;
            }
        }
    }
}

extern "C" void kernel_launch(void* const* d_in, const int* in_sizes, int n_in,
                              void* d_out, int out_size) {
    const float* x    = (const float*)d_in[0];  // [B,T,D]
    const int*   mask = (const int*)d_in[1];    // [B,T]
    const float* w    = (const float*)d_in[2];  // [D,U]
    const float* bias = (const float*)d_in[3];
    const float* lb   = (const float*)d_in[4];
    const float* rb   = (const float*)d_in[5];
    float* out = (float*)d_out;

    prep_w_kernel<<<(N_TOT * K_TOT + 255) / 256, 256>>>(w);

    static int configured = 0;
    if (!configured) {
        cudaFuncSetAttribute(crf_mma_kernel,
                             cudaFuncAttributeMaxDynamicSharedMemorySize, SM_TOTAL);
        configured = 1;
    }
    crf_mma_kernel<<<NTILES, NTHREADS, SM_TOTAL>>>(x, mask, bias, lb, rb, out);
}

// round 6
// speedup vs baseline: 3.0147x; 1.0004x over previous
#include <cuda_runtime.h>
#include <cuda_fp16.h>
#include <cstdint>

// CRF: energy[B,T,U] = x[B,T,D] @ w[D,U] + bias + start*lb + end*rb
// GEMM M=32768 K=1024 N=128 fp32 via mma.sync fp16 2-pass split:
//   acc = (A_hi + A_lo) * B, A split to fp16 hi/lo, B = fp16(w).
// R6: 512 threads / 16 warps (4x4 warp grid, 32x32 warp tile) to fix
// issue-bound profile (R5: 8 warps -> 2/SMSP, tensor pipe 41% idle-bound).

#define M_TOT 32768
#define K_TOT 1024
#define N_TOT 128
#define T_LEN 512
#define BM 128
#define BK 32
#define NCHUNK (K_TOT / BK)   // 32
#define NTILES (M_TOT / BM)   // 256
#define NTHREADS 512

#define ROWB 80                       // 80-byte row stride; ldsm conflict-free
#define TILE_BYTES (128 * ROWB)       // 10240
#define A_HI 0
#define A_LO TILE_BYTES
#define B_OFF (2 * TILE_BYTES)
#define BUF_STRIDE (3 * TILE_BYTES)   // 30720
#define SM_BIAS (2 * BUF_STRIDE)      // 61440
#define SM_LB   (SM_BIAS + 512)
#define SM_RB   (SM_BIAS + 1024)
#define SM_TOTAL (SM_BIAS + 1536)     // 62976 (dynamic)

__device__ __forceinline__ uint32_t smem_u32(const void* p) {
    uint32_t a;
    asm("{ .reg .u64 t; cvta.to.shared.u64 t, %1; cvt.u32.u64 %0, t; }" : "=r"(a) : "l"(p));
    return a;
}

__device__ __forceinline__ void ldsm_x4(uint32_t (&r)[4], uint32_t addr) {
    asm volatile("ldmatrix.sync.aligned.m8n8.x4.shared.b16 {%0,%1,%2,%3}, [%4];"
                 : "=r"(r[0]), "=r"(r[1]), "=r"(r[2]), "=r"(r[3]) : "r"(addr));
}

__device__ __forceinline__ void mma16816(float (&c)[4], const uint32_t (&a)[4],
                                         uint32_t b0, uint32_t b1) {
    asm volatile(
        "mma.sync.aligned.m16n8k16.row.col.f32.f16.f16.f32 "
        "{%0,%1,%2,%3}, {%4,%5,%6,%7}, {%8,%9}, {%0,%1,%2,%3};"
        : "+f"(c[0]), "+f"(c[1]), "+f"(c[2]), "+f"(c[3])
        : "r"(a[0]), "r"(a[1]), "r"(a[2]), "r"(a[3]), "r"(b0), "r"(b1));
}

__device__ __forceinline__ uint32_t pk(__half a, __half b) {
    __half2 t = __halves2half2(a, b);
    return *reinterpret_cast<uint32_t*>(&t);
}

// w transposed to [N, K] fp16 (K-major, "col" operand for mma.sync)
__device__ __align__(16) __half g_wh[N_TOT * K_TOT];

__global__ void prep_w_kernel(const float* __restrict__ w) {
    int idx = blockIdx.x * blockDim.x + threadIdx.x;   // n*1024 + k
    if (idx >= N_TOT * K_TOT) return;
    int n = idx >> 10, k = idx & 1023;
    g_wh[idx] = __float2half(w[(size_t)k * N_TOT + n]);
}

__global__ __launch_bounds__(NTHREADS)
void crf_mma_kernel(const float* __restrict__ x, const int* __restrict__ mask,
                    const float* __restrict__ bias, const float* __restrict__ lb,
                    const float* __restrict__ rb, float* __restrict__ out) {
    extern __shared__ __align__(128) char sm[];
    const uint32_t smb = smem_u32(sm);

    const int tid = threadIdx.x;
    const int wid = tid >> 5, lane = tid & 31;
    const int wm = wid & 3, wn = wid >> 2;      // 4 M-warps x 4 N-warps
    const int rowBase = blockIdx.x * BM;

    if (tid < N_TOT) {
        *(float*)(sm + SM_BIAS + tid * 4) = bias[tid];
        *(float*)(sm + SM_LB + tid * 4) = lb[tid];
        *(float*)(sm + SM_RB + tid * 4) = rb[tid];
    }

    float acc[2][4][4];
#pragma unroll
    for (int i = 0; i < 2; i++)
#pragma unroll
        for (int j = 0; j < 4; j++)
#pragma unroll
            for (int v = 0; v < 4; v++) acc[i][j][v] = 0.0f;

    // ldmatrix per-lane source rows
    const int grp = lane >> 3, lr = lane & 7;
    const uint32_t aRow = wm * 32 + (grp & 1) * 8 + lr;
    const uint32_t aKof = (grp >> 1) * 8;
    const uint32_t bRow = wn * 32 + (grp >> 1) * 8 + lr;
    const uint32_t bKof = (grp & 1) * 8;

    float4 aR[2];
    uint4 bR;

    auto load_regs = [&](int c) {
        const int kt = c * BK;
#pragma unroll
        for (int i = 0; i < 2; i++) {
            int idx = i * NTHREADS + tid;
            int r = idx >> 3, c4 = idx & 7;          // 128 rows x 8 float4
            aR[i] = *reinterpret_cast<const float4*>(
                x + (size_t)(rowBase + r) * K_TOT + kt + c4 * 4);
        }
        {
            int n = tid >> 2, q = tid & 3;           // 128 rows x 4 uint4
            bR = *reinterpret_cast<const uint4*>(g_wh + (size_t)n * K_TOT + kt + q * 8);
        }
    };
    auto sts_buf = [&](int buf) {
        char* base = sm + buf * BUF_STRIDE;
#pragma unroll
        for (int i = 0; i < 2; i++) {
            int idx = i * NTHREADS + tid;
            int r = idx >> 3, c4 = idx & 7;
            float4 v = aR[i];
            __half h0 = __float2half(v.x), h1 = __float2half(v.y);
            __half h2 = __float2half(v.z), h3 = __float2half(v.w);
            uint2 hh; hh.x = pk(h0, h1); hh.y = pk(h2, h3);
            uint2 ll;
            ll.x = pk(__float2half(v.x - __half2float(h0)),
                      __float2half(v.y - __half2float(h1)));
            ll.y = pk(__float2half(v.z - __half2float(h2)),
                      __float2half(v.w - __half2float(h3)));
            uint32_t off = (uint32_t)(r * ROWB + c4 * 8);
            *(uint2*)(base + A_HI + off) = hh;
            *(uint2*)(base + A_LO + off) = ll;
        }
        {
            int n = tid >> 2, q = tid & 3;
            *(uint4*)(base + B_OFF + (uint32_t)(n * ROWB + q * 16)) = bR;
        }
    };

    // ---- prologue ----
    load_regs(0);
    sts_buf(0);
    load_regs(1);
    __syncthreads();

#pragma unroll 1
    for (int c = 0; c < NCHUNK; c++) {
        const uint32_t cb = smb + (c & 1) * BUF_STRIDE;
        if (c + 1 < NCHUNK) sts_buf((c + 1) & 1);
        if (c + 2 < NCHUNK) load_regs(c + 2);

        // ---- compute chunk c: 2 k16-steps, hi then lo pass ----
#pragma unroll
        for (int ks = 0; ks < 2; ks++) {
            uint32_t af[2][2][4];   // [mt][hi/lo]
#pragma unroll
            for (int mt = 0; mt < 2; mt++) {
                uint32_t ao = (aRow + mt * 16) * ROWB + (ks * 16 + aKof) * 2;
                ldsm_x4(af[mt][0], cb + A_HI + ao);
                ldsm_x4(af[mt][1], cb + A_LO + ao);
            }
            uint32_t bf[2][4];
#pragma unroll
            for (int np = 0; np < 2; np++) {
                uint32_t bo = (bRow + np * 16) * ROWB + (ks * 16 + bKof) * 2;
                ldsm_x4(bf[np], cb + B_OFF + bo);
            }
#pragma unroll
            for (int mt = 0; mt < 2; mt++)
#pragma unroll
                for (int np = 0; np < 2; np++) {
                    mma16816(acc[mt][2 * np + 0], af[mt][0], bf[np][0], bf[np][1]);
                    mma16816(acc[mt][2 * np + 1], af[mt][0], bf[np][2], bf[np][3]);
                }
#pragma unroll
            for (int mt = 0; mt < 2; mt++)
#pragma unroll
                for (int np = 0; np < 2; np++) {
                    mma16816(acc[mt][2 * np + 0], af[mt][1], bf[np][0], bf[np][1]);
                    mma16816(acc[mt][2 * np + 1], af[mt][1], bf[np][2], bf[np][3]);
                }
        }
        __syncthreads();
    }

    // ---- fused epilogue ----
    const float* sb = (const float*)(sm + SM_BIAS);
    const float* sl = (const float*)(sm + SM_LB);
    const float* sr = (const float*)(sm + SM_RB);
    const int colBase = wn * 32 + (lane & 3) * 2;
#pragma unroll
    for (int mt = 0; mt < 2; mt++) {
#pragma unroll
        for (int h = 0; h < 2; h++) {
            int m = rowBase + wm * 32 + mt * 16 + h * 8 + (lane >> 2);
            int bb = m >> 9, t = m & (T_LEN - 1);
            const int* mrow = mask + bb * T_LEN;
            int mv = mrow[t];
            int prev = t ? mrow[t - 1] : 0;
            int nxt = (t < T_LEN - 1) ? mrow[t + 1] : 0;
            float sf = (mv > prev) ? 1.0f : 0.0f;
            float ef = (nxt > mv) ? 1.0f : 0.0f;
            float* orow = out + (size_t)m * N_TOT;
#pragma unroll
            for (int nt = 0; nt < 4; nt++) {
                int col = colBase + nt * 8;
                float2 v;
                v.x = acc[mt][nt][h * 2 + 0] + sb[col] + sf * sl[col] + ef * sr[col];
                v.y = acc[mt][nt][h * 2 + 1] + sb[col + 1] + sf * sl[col + 1] + ef * sr[col + 1];
                *reinterpret_cast<float2*>(orow + col) = v;
            }
        }
    }
}

extern "C" void kernel_launch(void* const* d_in, const int* in_sizes, int n_in,
                              void* d_out, int out_size) {
    const float* x    = (const float*)d_in[0];  // [B,T,D]
    const int*   mask = (const int*)d_in[1];    // [B,T]
    const float* w    = (const float*)d_in[2];  // [D,U]
    const float* bias = (const float*)d_in[3];
    const float* lb   = (const float*)d_in[4];
    const float* rb   = (const float*)d_in[5];
    float* out = (float*)d_out;

    prep_w_kernel<<<(N_TOT * K_TOT + 255) / 256, 256>>>(w);

    static int configured = 0;
    if (!configured) {
        cudaFuncSetAttribute(crf_mma_kernel,
                             cudaFuncAttributeMaxDynamicSharedMemorySize, SM_TOTAL);
        configured = 1;
    }
    crf_mma_kernel<<<NTILES, NTHREADS, SM_TOTAL>>>(x, mask, bias, lb, rb, out);
}